// round 8
// baseline (speedup 1.0000x reference)
#include <cuda_runtime.h>
#include <math.h>

#define BZ 2
#define NS 2048
#define CD 1024
#define HH 16
#define DD 64
#define ROWS (BZ*NS)   // 4096

// Scratch (device globals; no allocation allowed)
__device__ float g_Q [ROWS*CD];      // 16 MB  post-proj Q (RoPE'd in place)
__device__ float g_KV[ROWS*2*DD];    //  2 MB  per row: K[64] | V[64] (g-summed)
__device__ float g_W [CD*2*DD];      // 512 KB effective KV weight (g-summed)
__device__ float g_A [ROWS*CD];      // 16 MB  attention output [B*N, H*D]

// ---------------------------------------------------------------------------
// Fold the kv-head sum into the weight: W_eff[c][j] (j<64 -> K, j>=64 -> V)
// ---------------------------------------------------------------------------
__global__ void weff_kernel(const float* __restrict__ wkv) {
    int idx = blockIdx.x * blockDim.x + threadIdx.x;
    if (idx >= CD * 128) return;
    int c = idx >> 7, j = idx & 127;
    const float* b = wkv + (size_t)c * 512 + ((j < 64) ? j : (256 + (j - 64)));
    g_W[idx] = b[0] + b[64] + b[128] + b[192];
}

// ---------------------------------------------------------------------------
// Classic 128x128x8 SGEMM, 256 threads, 8x8 per thread. Row-major A[MxK],
// B[KxN], C[MxN]. M,N,K multiples of 128/128/8 (true for all 3 calls).
// ---------------------------------------------------------------------------
__global__ __launch_bounds__(256) void sgemm128(
    const float* __restrict__ A, const float* __restrict__ Bm,
    float* __restrict__ Cm, int M, int Nn, int K)
{
    __shared__ float As[8][128];
    __shared__ float Bs[8][128];
    const int brow = blockIdx.y * 128;
    const int bcol = blockIdx.x * 128;
    const int tid  = threadIdx.x;

    const int a_r = tid >> 1,  a_k = (tid & 1) * 4;   // A tile 128x8 via float4
    const int b_k = tid >> 5,  b_c = (tid & 31) * 4;  // B tile 8x128 via float4
    const int ty  = tid >> 4,  tx  = tid & 15;

    float acc[8][8];
    #pragma unroll
    for (int i = 0; i < 8; i++)
        #pragma unroll
        for (int j = 0; j < 8; j++) acc[i][j] = 0.f;

    for (int k0 = 0; k0 < K; k0 += 8) {
        float4 av = *(const float4*)(A + (size_t)(brow + a_r) * K + k0 + a_k);
        As[a_k + 0][a_r] = av.x; As[a_k + 1][a_r] = av.y;
        As[a_k + 2][a_r] = av.z; As[a_k + 3][a_r] = av.w;
        *(float4*)(&Bs[b_k][b_c]) =
            *(const float4*)(Bm + (size_t)(k0 + b_k) * Nn + bcol + b_c);
        __syncthreads();

        #pragma unroll
        for (int kk = 0; kk < 8; kk++) {
            float ar[8], br[8];
            *(float4*)(ar)     = *(const float4*)(&As[kk][ty * 8]);
            *(float4*)(ar + 4) = *(const float4*)(&As[kk][ty * 8 + 4]);
            *(float4*)(br)     = *(const float4*)(&Bs[kk][tx * 8]);
            *(float4*)(br + 4) = *(const float4*)(&Bs[kk][tx * 8 + 4]);
            #pragma unroll
            for (int i = 0; i < 8; i++)
                #pragma unroll
                for (int j = 0; j < 8; j++)
                    acc[i][j] += ar[i] * br[j];
        }
        __syncthreads();
    }

    #pragma unroll
    for (int i = 0; i < 8; i++) {
        float4* dst = (float4*)(Cm + (size_t)(brow + ty * 8 + i) * Nn + bcol + tx * 8);
        dst[0] = make_float4(acc[i][0], acc[i][1], acc[i][2], acc[i][3]);
        dst[1] = make_float4(acc[i][4], acc[i][5], acc[i][6], acc[i][7]);
    }
}

// ---------------------------------------------------------------------------
// RoPE in place. One thread per (row, head, pair i in [0,32)).
// Angle computed in double: pos (<=2047) amplifies inv_freq rounding, double
// keeps us ~30x under the error budget.
// ---------------------------------------------------------------------------
__global__ void rope_kernel(float* buf, int rowStride, int nHeads) {
    int idx = blockIdx.x * blockDim.x + threadIdx.x;
    int total = ROWS * nHeads * 32;
    if (idx >= total) return;
    int i   = idx & 31;
    int h   = (idx >> 5) % nHeads;
    int row = idx / (32 * nHeads);
    int pos = row & (NS - 1);

    double inv = pow(10000.0, -(double)(2 * i) / (double)DD);
    double ang = (double)pos * inv;
    float c = (float)cos(ang), s = (float)sin(ang);

    float* p1 = buf + (size_t)row * rowStride + h * DD + i;
    float* p2 = p1 + 32;
    float x1 = *p1, x2 = *p2;
    *p1 = x1 * c - x2 * s;
    *p2 = x2 * c + x1 * s;
}

// ---------------------------------------------------------------------------
// Flash attention, single (g-summed) KV head shared by all 16 query heads.
// 1 thread = 1 query row. q (pre-scaled) and o live in registers; K/V tiles
// (64 rows x 64) in smem; all smem reads are warp-broadcast float4.
// Softmax rescale only on new max (rare: ~ln(N) per row).
// grid = (NS/128, HH, BZ), block = 128.
// ---------------------------------------------------------------------------
__global__ __launch_bounds__(128) void flash_kernel() {
    __shared__ float Ks[64][64];
    __shared__ float Vs[64][64];

    const int t = threadIdx.x;
    const int n = blockIdx.x * 128 + t;
    const int h = blockIdx.y;
    const int b = blockIdx.z;

    const float* qptr = g_Q + ((size_t)(b * NS + n)) * CD + h * DD;
    float qr[64], o[64];
    #pragma unroll
    for (int d4 = 0; d4 < 16; d4++) {
        float4 v = ((const float4*)qptr)[d4];
        qr[d4*4+0] = v.x * 0.125f; qr[d4*4+1] = v.y * 0.125f;
        qr[d4*4+2] = v.z * 0.125f; qr[d4*4+3] = v.w * 0.125f;
    }
    #pragma unroll
    for (int d = 0; d < 64; d++) o[d] = 0.f;

    float m = -INFINITY, l = 0.f;
    const float* KVb = g_KV + (size_t)b * NS * 128;

    for (int jt = 0; jt < NS; jt += 64) {
        // cooperative tile load: 64 rows x (16 f4 K + 16 f4 V)
        #pragma unroll
        for (int i2 = 0; i2 < 8; i2++) {
            int flat = t + i2 * 128;            // 0..1023
            int j = flat >> 4, d4 = flat & 15;
            const float4* src = (const float4*)(KVb + (size_t)(jt + j) * 128);
            ((float4*)Ks[j])[d4] = src[d4];
            ((float4*)Vs[j])[d4] = src[16 + d4];
        }
        __syncthreads();

        for (int j = 0; j < 64; j++) {
            const float4* kr = (const float4*)Ks[j];
            float a0 = 0.f, a1 = 0.f, a2 = 0.f, a3 = 0.f;
            #pragma unroll
            for (int d4 = 0; d4 < 16; d4 += 4) {
                float4 k0 = kr[d4+0];
                a0 += qr[(d4+0)*4+0]*k0.x + qr[(d4+0)*4+1]*k0.y
                    + qr[(d4+0)*4+2]*k0.z + qr[(d4+0)*4+3]*k0.w;
                float4 k1 = kr[d4+1];
                a1 += qr[(d4+1)*4+0]*k1.x + qr[(d4+1)*4+1]*k1.y
                    + qr[(d4+1)*4+2]*k1.z + qr[(d4+1)*4+3]*k1.w;
                float4 k2 = kr[d4+2];
                a2 += qr[(d4+2)*4+0]*k2.x + qr[(d4+2)*4+1]*k2.y
                    + qr[(d4+2)*4+2]*k2.z + qr[(d4+2)*4+3]*k2.w;
                float4 k3 = kr[d4+3];
                a3 += qr[(d4+3)*4+0]*k3.x + qr[(d4+3)*4+1]*k3.y
                    + qr[(d4+3)*4+2]*k3.z + qr[(d4+3)*4+3]*k3.w;
            }
            float s = (a0 + a1) + (a2 + a3);

            if (s > m) {                      // rare rescale path
                float corr = __expf(m - s);
                m = s;
                l *= corr;
                #pragma unroll
                for (int d = 0; d < 64; d++) o[d] *= corr;
            }
            float p = __expf(s - m);
            l += p;
            const float4* vr = (const float4*)Vs[j];
            #pragma unroll
            for (int d4 = 0; d4 < 16; d4++) {
                float4 vv = vr[d4];
                o[d4*4+0] += p * vv.x; o[d4*4+1] += p * vv.y;
                o[d4*4+2] += p * vv.z; o[d4*4+3] += p * vv.w;
            }
        }
        __syncthreads();
    }

    float inv = 1.f / l;
    float* optr = g_A + ((size_t)(b * NS + n)) * CD + h * DD;
    #pragma unroll
    for (int d4 = 0; d4 < 16; d4++) {
        ((float4*)optr)[d4] = make_float4(o[d4*4+0]*inv, o[d4*4+1]*inv,
                                          o[d4*4+2]*inv, o[d4*4+3]*inv);
    }
}

// ---------------------------------------------------------------------------
extern "C" void kernel_launch(void* const* d_in, const int* in_sizes, int n_in,
                              void* d_out, int out_size) {
    const float* x    = (const float*)d_in[0];
    const float* wq   = (const float*)d_in[1];
    const float* wkv  = (const float*)d_in[2];
    const float* wout = (const float*)d_in[3];
    float* out = (float*)d_out;

    float *Q, *KV, *W, *A;
    cudaGetSymbolAddress((void**)&Q,  g_Q);
    cudaGetSymbolAddress((void**)&KV, g_KV);
    cudaGetSymbolAddress((void**)&W,  g_W);
    cudaGetSymbolAddress((void**)&A,  g_A);

    // 1) fold kv-head sum into weight
    weff_kernel<<<(CD * 128) / 256, 256>>>(wkv);

    // 2) Q = x @ w_q   [4096x1024] = [4096x1024]@[1024x1024]
    dim3 gQ(CD / 128, ROWS / 128);
    sgemm128<<<gQ, 256>>>(x, wq, Q, ROWS, CD, CD);

    // 3) KV = x @ W_eff   [4096x128]
    dim3 gKV(1, ROWS / 128);
    sgemm128<<<gKV, 256>>>(x, W, KV, ROWS, 128, CD);

    // 4) RoPE on Q (16 heads) and on K half of KV (1 head)
    rope_kernel<<<(ROWS * HH * 32) / 256, 256>>>(Q, CD, HH);
    rope_kernel<<<(ROWS * 32) / 256, 256>>>(KV, 128, 1);

    // 5) flash attention -> g_A  [B*N, H*D]
    dim3 gF(NS / 128, HH, BZ);
    flash_kernel<<<gF, 128>>>();

    // 6) out = A @ w_out
    sgemm128<<<gQ, 256>>>(A, wout, out, ROWS, CD, CD);
}

// round 11
// speedup vs baseline: 1.0019x; 1.0019x over previous
#include <cuda_runtime.h>
#include <math.h>

#define BZ 2
#define NS 2048
#define CD 1024
#define HH 16
#define DD 64
#define ROWS (BZ*NS)   // 4096

// Scratch (device globals; no allocation allowed)
__device__ float g_Q [ROWS*CD];      // 16 MB  post-proj Q (RoPE'd in place)
__device__ float g_KV[ROWS*2*DD];    //  2 MB  per row: K[64] | V[64] (g-summed)
__device__ float g_W [CD*2*DD];      // 512 KB effective KV weight (g-summed)
__device__ float g_A [ROWS*CD];      // 16 MB  attention output [B*N, H*D]

// ---------------------------------------------------------------------------
// Fold the kv-head sum into the weight: W_eff[c][j] (j<64 -> K, j>=64 -> V)
// ---------------------------------------------------------------------------
__global__ void weff_kernel(const float* __restrict__ wkv) {
    int idx = blockIdx.x * blockDim.x + threadIdx.x;
    if (idx >= CD * 128) return;
    int c = idx >> 7, j = idx & 127;
    const float* b = wkv + (size_t)c * 512 + ((j < 64) ? j : (256 + (j - 64)));
    g_W[idx] = b[0] + b[64] + b[128] + b[192];
}

// ---------------------------------------------------------------------------
// Classic 128x128x8 SGEMM, 256 threads, 8x8 per thread. Row-major A[MxK],
// B[KxN], C[MxN]. M,N,K multiples of 128/128/8 (true for all 3 calls).
// ---------------------------------------------------------------------------
__global__ __launch_bounds__(256) void sgemm128(
    const float* __restrict__ A, const float* __restrict__ Bm,
    float* __restrict__ Cm, int M, int Nn, int K)
{
    __shared__ float As[8][128];
    __shared__ float Bs[8][128];
    const int brow = blockIdx.y * 128;
    const int bcol = blockIdx.x * 128;
    const int tid  = threadIdx.x;

    const int a_r = tid >> 1,  a_k = (tid & 1) * 4;   // A tile 128x8 via float4
    const int b_k = tid >> 5,  b_c = (tid & 31) * 4;  // B tile 8x128 via float4
    const int ty  = tid >> 4,  tx  = tid & 15;

    float acc[8][8];
    #pragma unroll
    for (int i = 0; i < 8; i++)
        #pragma unroll
        for (int j = 0; j < 8; j++) acc[i][j] = 0.f;

    for (int k0 = 0; k0 < K; k0 += 8) {
        float4 av = *(const float4*)(A + (size_t)(brow + a_r) * K + k0 + a_k);
        As[a_k + 0][a_r] = av.x; As[a_k + 1][a_r] = av.y;
        As[a_k + 2][a_r] = av.z; As[a_k + 3][a_r] = av.w;
        *(float4*)(&Bs[b_k][b_c]) =
            *(const float4*)(Bm + (size_t)(k0 + b_k) * Nn + bcol + b_c);
        __syncthreads();

        #pragma unroll
        for (int kk = 0; kk < 8; kk++) {
            float ar[8], br[8];
            *(float4*)(ar)     = *(const float4*)(&As[kk][ty * 8]);
            *(float4*)(ar + 4) = *(const float4*)(&As[kk][ty * 8 + 4]);
            *(float4*)(br)     = *(const float4*)(&Bs[kk][tx * 8]);
            *(float4*)(br + 4) = *(const float4*)(&Bs[kk][tx * 8 + 4]);
            #pragma unroll
            for (int i = 0; i < 8; i++)
                #pragma unroll
                for (int j = 0; j < 8; j++)
                    acc[i][j] += ar[i] * br[j];
        }
        __syncthreads();
    }

    #pragma unroll
    for (int i = 0; i < 8; i++) {
        float4* dst = (float4*)(Cm + (size_t)(brow + ty * 8 + i) * Nn + bcol + tx * 8);
        dst[0] = make_float4(acc[i][0], acc[i][1], acc[i][2], acc[i][3]);
        dst[1] = make_float4(acc[i][4], acc[i][5], acc[i][6], acc[i][7]);
    }
}

// ---------------------------------------------------------------------------
// RoPE in place. One thread per (row, head, pair i in [0,32)).
// Angle computed in double: pos (<=2047) amplifies inv_freq rounding, double
// keeps us ~30x under the error budget.
// ---------------------------------------------------------------------------
__global__ void rope_kernel(float* buf, int rowStride, int nHeads) {
    int idx = blockIdx.x * blockDim.x + threadIdx.x;
    int total = ROWS * nHeads * 32;
    if (idx >= total) return;
    int i   = idx & 31;
    int h   = (idx >> 5) % nHeads;
    int row = idx / (32 * nHeads);
    int pos = row & (NS - 1);

    double inv = pow(10000.0, -(double)(2 * i) / (double)DD);
    double ang = (double)pos * inv;
    float c = (float)cos(ang), s = (float)sin(ang);

    float* p1 = buf + (size_t)row * rowStride + h * DD + i;
    float* p2 = p1 + 32;
    float x1 = *p1, x2 = *p2;
    *p1 = x1 * c - x2 * s;
    *p2 = x2 * c + x1 * s;
}

// ---------------------------------------------------------------------------
// Flash attention, single (g-summed) KV head shared by all 16 query heads.
// 1 thread = 1 query row. q (pre-scaled) and o live in registers; K/V tiles
// (64 rows x 64) in smem; all smem reads are warp-broadcast float4.
// Softmax rescale only on new max (rare: ~ln(N) per row).
// grid = (NS/128, HH, BZ), block = 128.
// ---------------------------------------------------------------------------
__global__ __launch_bounds__(128) void flash_kernel() {
    __shared__ float Ks[64][64];
    __shared__ float Vs[64][64];

    const int t = threadIdx.x;
    const int n = blockIdx.x * 128 + t;
    const int h = blockIdx.y;
    const int b = blockIdx.z;

    const float* qptr = g_Q + ((size_t)(b * NS + n)) * CD + h * DD;
    float qr[64], o[64];
    #pragma unroll
    for (int d4 = 0; d4 < 16; d4++) {
        float4 v = ((const float4*)qptr)[d4];
        qr[d4*4+0] = v.x * 0.125f; qr[d4*4+1] = v.y * 0.125f;
        qr[d4*4+2] = v.z * 0.125f; qr[d4*4+3] = v.w * 0.125f;
    }
    #pragma unroll
    for (int d = 0; d < 64; d++) o[d] = 0.f;

    float m = -INFINITY, l = 0.f;
    const float* KVb = g_KV + (size_t)b * NS * 128;

    for (int jt = 0; jt < NS; jt += 64) {
        // cooperative tile load: 64 rows x (16 f4 K + 16 f4 V)
        #pragma unroll
        for (int i2 = 0; i2 < 8; i2++) {
            int flat = t + i2 * 128;            // 0..1023
            int j = flat >> 4, d4 = flat & 15;
            const float4* src = (const float4*)(KVb + (size_t)(jt + j) * 128);
            ((float4*)Ks[j])[d4] = src[d4];
            ((float4*)Vs[j])[d4] = src[16 + d4];
        }
        __syncthreads();

        for (int j = 0; j < 64; j++) {
            const float4* kr = (const float4*)Ks[j];
            float a0 = 0.f, a1 = 0.f, a2 = 0.f, a3 = 0.f;
            #pragma unroll
            for (int d4 = 0; d4 < 16; d4 += 4) {
                float4 k0 = kr[d4+0];
                a0 += qr[(d4+0)*4+0]*k0.x + qr[(d4+0)*4+1]*k0.y
                    + qr[(d4+0)*4+2]*k0.z + qr[(d4+0)*4+3]*k0.w;
                float4 k1 = kr[d4+1];
                a1 += qr[(d4+1)*4+0]*k1.x + qr[(d4+1)*4+1]*k1.y
                    + qr[(d4+1)*4+2]*k1.z + qr[(d4+1)*4+3]*k1.w;
                float4 k2 = kr[d4+2];
                a2 += qr[(d4+2)*4+0]*k2.x + qr[(d4+2)*4+1]*k2.y
                    + qr[(d4+2)*4+2]*k2.z + qr[(d4+2)*4+3]*k2.w;
                float4 k3 = kr[d4+3];
                a3 += qr[(d4+3)*4+0]*k3.x + qr[(d4+3)*4+1]*k3.y
                    + qr[(d4+3)*4+2]*k3.z + qr[(d4+3)*4+3]*k3.w;
            }
            float s = (a0 + a1) + (a2 + a3);

            if (s > m) {                      // rare rescale path
                float corr = __expf(m - s);
                m = s;
                l *= corr;
                #pragma unroll
                for (int d = 0; d < 64; d++) o[d] *= corr;
            }
            float p = __expf(s - m);
            l += p;
            const float4* vr = (const float4*)Vs[j];
            #pragma unroll
            for (int d4 = 0; d4 < 16; d4++) {
                float4 vv = vr[d4];
                o[d4*4+0] += p * vv.x; o[d4*4+1] += p * vv.y;
                o[d4*4+2] += p * vv.z; o[d4*4+3] += p * vv.w;
            }
        }
        __syncthreads();
    }

    float inv = 1.f / l;
    float* optr = g_A + ((size_t)(b * NS + n)) * CD + h * DD;
    #pragma unroll
    for (int d4 = 0; d4 < 16; d4++) {
        ((float4*)optr)[d4] = make_float4(o[d4*4+0]*inv, o[d4*4+1]*inv,
                                          o[d4*4+2]*inv, o[d4*4+3]*inv);
    }
}

// ---------------------------------------------------------------------------
extern "C" void kernel_launch(void* const* d_in, const int* in_sizes, int n_in,
                              void* d_out, int out_size) {
    const float* x    = (const float*)d_in[0];
    const float* wq   = (const float*)d_in[1];
    const float* wkv  = (const float*)d_in[2];
    const float* wout = (const float*)d_in[3];
    float* out = (float*)d_out;

    float *Q, *KV, *W, *A;
    cudaGetSymbolAddress((void**)&Q,  g_Q);
    cudaGetSymbolAddress((void**)&KV, g_KV);
    cudaGetSymbolAddress((void**)&W,  g_W);
    cudaGetSymbolAddress((void**)&A,  g_A);

    // 1) fold kv-head sum into weight
    weff_kernel<<<(CD * 128) / 256, 256>>>(wkv);

    // 2) Q = x @ w_q   [4096x1024] = [4096x1024]@[1024x1024]
    dim3 gQ(CD / 128, ROWS / 128);
    sgemm128<<<gQ, 256>>>(x, wq, Q, ROWS, CD, CD);

    // 3) KV = x @ W_eff   [4096x128]
    dim3 gKV(1, ROWS / 128);
    sgemm128<<<gKV, 256>>>(x, W, KV, ROWS, 128, CD);

    // 4) RoPE on Q (16 heads) and on K half of KV (1 head)
    rope_kernel<<<(ROWS * HH * 32) / 256, 256>>>(Q, CD, HH);
    rope_kernel<<<(ROWS * 32) / 256, 256>>>(KV, 128, 1);

    // 5) flash attention -> g_A  [B*N, H*D]
    dim3 gF(NS / 128, HH, BZ);
    flash_kernel<<<gF, 128>>>();

    // 6) out = A @ w_out
    sgemm128<<<gQ, 256>>>(A, wout, out, ROWS, CD, CD);
}

// round 15
// speedup vs baseline: 1.0021x; 1.0002x over previous
#include <cuda_runtime.h>
#include <math.h>

#define BZ 2
#define NS 2048
#define CD 1024
#define HH 16
#define DD 64
#define ROWS (BZ*NS)   // 4096

// Scratch (device globals; no allocation allowed)
__device__ float g_Q [ROWS*CD];      // 16 MB  post-proj Q (RoPE'd in place)
__device__ float g_KV[ROWS*2*DD];    //  2 MB  per row: K[64] | V[64] (g-summed)
__device__ float g_W [CD*2*DD];      // 512 KB effective KV weight (g-summed)
__device__ float g_A [ROWS*CD];      // 16 MB  attention output [B*N, H*D]

// ---------------------------------------------------------------------------
// Fold the kv-head sum into the weight: W_eff[c][j] (j<64 -> K, j>=64 -> V)
// ---------------------------------------------------------------------------
__global__ void weff_kernel(const float* __restrict__ wkv) {
    int idx = blockIdx.x * blockDim.x + threadIdx.x;
    if (idx >= CD * 128) return;
    int c = idx >> 7, j = idx & 127;
    const float* b = wkv + (size_t)c * 512 + ((j < 64) ? j : (256 + (j - 64)));
    g_W[idx] = b[0] + b[64] + b[128] + b[192];
}

// ---------------------------------------------------------------------------
// Classic 128x128x8 SGEMM, 256 threads, 8x8 per thread. Row-major A[MxK],
// B[KxN], C[MxN]. M,N,K multiples of 128/128/8 (true for all 3 calls).
// ---------------------------------------------------------------------------
__global__ __launch_bounds__(256) void sgemm128(
    const float* __restrict__ A, const float* __restrict__ Bm,
    float* __restrict__ Cm, int M, int Nn, int K)
{
    __shared__ float As[8][128];
    __shared__ float Bs[8][128];
    const int brow = blockIdx.y * 128;
    const int bcol = blockIdx.x * 128;
    const int tid  = threadIdx.x;

    const int a_r = tid >> 1,  a_k = (tid & 1) * 4;   // A tile 128x8 via float4
    const int b_k = tid >> 5,  b_c = (tid & 31) * 4;  // B tile 8x128 via float4
    const int ty  = tid >> 4,  tx  = tid & 15;

    float acc[8][8];
    #pragma unroll
    for (int i = 0; i < 8; i++)
        #pragma unroll
        for (int j = 0; j < 8; j++) acc[i][j] = 0.f;

    for (int k0 = 0; k0 < K; k0 += 8) {
        float4 av = *(const float4*)(A + (size_t)(brow + a_r) * K + k0 + a_k);
        As[a_k + 0][a_r] = av.x; As[a_k + 1][a_r] = av.y;
        As[a_k + 2][a_r] = av.z; As[a_k + 3][a_r] = av.w;
        *(float4*)(&Bs[b_k][b_c]) =
            *(const float4*)(Bm + (size_t)(k0 + b_k) * Nn + bcol + b_c);
        __syncthreads();

        #pragma unroll
        for (int kk = 0; kk < 8; kk++) {
            float ar[8], br[8];
            *(float4*)(ar)     = *(const float4*)(&As[kk][ty * 8]);
            *(float4*)(ar + 4) = *(const float4*)(&As[kk][ty * 8 + 4]);
            *(float4*)(br)     = *(const float4*)(&Bs[kk][tx * 8]);
            *(float4*)(br + 4) = *(const float4*)(&Bs[kk][tx * 8 + 4]);
            #pragma unroll
            for (int i = 0; i < 8; i++)
                #pragma unroll
                for (int j = 0; j < 8; j++)
                    acc[i][j] += ar[i] * br[j];
        }
        __syncthreads();
    }

    #pragma unroll
    for (int i = 0; i < 8; i++) {
        float4* dst = (float4*)(Cm + (size_t)(brow + ty * 8 + i) * Nn + bcol + tx * 8);
        dst[0] = make_float4(acc[i][0], acc[i][1], acc[i][2], acc[i][3]);
        dst[1] = make_float4(acc[i][4], acc[i][5], acc[i][6], acc[i][7]);
    }
}

// ---------------------------------------------------------------------------
// RoPE in place. One thread per (row, head, pair i in [0,32)).
// Angle computed in double: pos (<=2047) amplifies inv_freq rounding, double
// keeps us ~30x under the error budget.
// ---------------------------------------------------------------------------
__global__ void rope_kernel(float* buf, int rowStride, int nHeads) {
    int idx = blockIdx.x * blockDim.x + threadIdx.x;
    int total = ROWS * nHeads * 32;
    if (idx >= total) return;
    int i   = idx & 31;
    int h   = (idx >> 5) % nHeads;
    int row = idx / (32 * nHeads);
    int pos = row & (NS - 1);

    double inv = pow(10000.0, -(double)(2 * i) / (double)DD);
    double ang = (double)pos * inv;
    float c = (float)cos(ang), s = (float)sin(ang);

    float* p1 = buf + (size_t)row * rowStride + h * DD + i;
    float* p2 = p1 + 32;
    float x1 = *p1, x2 = *p2;
    *p1 = x1 * c - x2 * s;
    *p2 = x2 * c + x1 * s;
}

// ---------------------------------------------------------------------------
// Flash attention, single (g-summed) KV head shared by all 16 query heads.
// 1 thread = 1 query row. q (pre-scaled) and o live in registers; K/V tiles
// (64 rows x 64) in smem; all smem reads are warp-broadcast float4.
// Softmax rescale only on new max (rare: ~ln(N) per row).
// grid = (NS/128, HH, BZ), block = 128.
// ---------------------------------------------------------------------------
__global__ __launch_bounds__(128) void flash_kernel() {
    __shared__ float Ks[64][64];
    __shared__ float Vs[64][64];

    const int t = threadIdx.x;
    const int n = blockIdx.x * 128 + t;
    const int h = blockIdx.y;
    const int b = blockIdx.z;

    const float* qptr = g_Q + ((size_t)(b * NS + n)) * CD + h * DD;
    float qr[64], o[64];
    #pragma unroll
    for (int d4 = 0; d4 < 16; d4++) {
        float4 v = ((const float4*)qptr)[d4];
        qr[d4*4+0] = v.x * 0.125f; qr[d4*4+1] = v.y * 0.125f;
        qr[d4*4+2] = v.z * 0.125f; qr[d4*4+3] = v.w * 0.125f;
    }
    #pragma unroll
    for (int d = 0; d < 64; d++) o[d] = 0.f;

    float m = -INFINITY, l = 0.f;
    const float* KVb = g_KV + (size_t)b * NS * 128;

    for (int jt = 0; jt < NS; jt += 64) {
        // cooperative tile load: 64 rows x (16 f4 K + 16 f4 V)
        #pragma unroll
        for (int i2 = 0; i2 < 8; i2++) {
            int flat = t + i2 * 128;            // 0..1023
            int j = flat >> 4, d4 = flat & 15;
            const float4* src = (const float4*)(KVb + (size_t)(jt + j) * 128);
            ((float4*)Ks[j])[d4] = src[d4];
            ((float4*)Vs[j])[d4] = src[16 + d4];
        }
        __syncthreads();

        for (int j = 0; j < 64; j++) {
            const float4* kr = (const float4*)Ks[j];
            float a0 = 0.f, a1 = 0.f, a2 = 0.f, a3 = 0.f;
            #pragma unroll
            for (int d4 = 0; d4 < 16; d4 += 4) {
                float4 k0 = kr[d4+0];
                a0 += qr[(d4+0)*4+0]*k0.x + qr[(d4+0)*4+1]*k0.y
                    + qr[(d4+0)*4+2]*k0.z + qr[(d4+0)*4+3]*k0.w;
                float4 k1 = kr[d4+1];
                a1 += qr[(d4+1)*4+0]*k1.x + qr[(d4+1)*4+1]*k1.y
                    + qr[(d4+1)*4+2]*k1.z + qr[(d4+1)*4+3]*k1.w;
                float4 k2 = kr[d4+2];
                a2 += qr[(d4+2)*4+0]*k2.x + qr[(d4+2)*4+1]*k2.y
                    + qr[(d4+2)*4+2]*k2.z + qr[(d4+2)*4+3]*k2.w;
                float4 k3 = kr[d4+3];
                a3 += qr[(d4+3)*4+0]*k3.x + qr[(d4+3)*4+1]*k3.y
                    + qr[(d4+3)*4+2]*k3.z + qr[(d4+3)*4+3]*k3.w;
            }
            float s = (a0 + a1) + (a2 + a3);

            if (s > m) {                      // rare rescale path
                float corr = __expf(m - s);
                m = s;
                l *= corr;
                #pragma unroll
                for (int d = 0; d < 64; d++) o[d] *= corr;
            }
            float p = __expf(s - m);
            l += p;
            const float4* vr = (const float4*)Vs[j];
            #pragma unroll
            for (int d4 = 0; d4 < 16; d4++) {
                float4 vv = vr[d4];
                o[d4*4+0] += p * vv.x; o[d4*4+1] += p * vv.y;
                o[d4*4+2] += p * vv.z; o[d4*4+3] += p * vv.w;
            }
        }
        __syncthreads();
    }

    float inv = 1.f / l;
    float* optr = g_A + ((size_t)(b * NS + n)) * CD + h * DD;
    #pragma unroll
    for (int d4 = 0; d4 < 16; d4++) {
        ((float4*)optr)[d4] = make_float4(o[d4*4+0]*inv, o[d4*4+1]*inv,
                                          o[d4*4+2]*inv, o[d4*4+3]*inv);
    }
}

// ---------------------------------------------------------------------------
extern "C" void kernel_launch(void* const* d_in, const int* in_sizes, int n_in,
                              void* d_out, int out_size) {
    const float* x    = (const float*)d_in[0];
    const float* wq   = (const float*)d_in[1];
    const float* wkv  = (const float*)d_in[2];
    const float* wout = (const float*)d_in[3];
    float* out = (float*)d_out;

    float *Q, *KV, *W, *A;
    cudaGetSymbolAddress((void**)&Q,  g_Q);
    cudaGetSymbolAddress((void**)&KV, g_KV);
    cudaGetSymbolAddress((void**)&W,  g_W);
    cudaGetSymbolAddress((void**)&A,  g_A);

    // 1) fold kv-head sum into weight
    weff_kernel<<<(CD * 128) / 256, 256>>>(wkv);

    // 2) Q = x @ w_q   [4096x1024] = [4096x1024]@[1024x1024]
    dim3 gQ(CD / 128, ROWS / 128);
    sgemm128<<<gQ, 256>>>(x, wq, Q, ROWS, CD, CD);

    // 3) KV = x @ W_eff   [4096x128]
    dim3 gKV(1, ROWS / 128);
    sgemm128<<<gKV, 256>>>(x, W, KV, ROWS, 128, CD);

    // 4) RoPE on Q (16 heads) and on K half of KV (1 head)
    rope_kernel<<<(ROWS * HH * 32) / 256, 256>>>(Q, CD, HH);
    rope_kernel<<<(ROWS * 32) / 256, 256>>>(KV, 128, 1);

    // 5) flash attention -> g_A  [B*N, H*D]
    dim3 gF(NS / 128, HH, BZ);
    flash_kernel<<<gF, 128>>>();

    // 6) out = A @ w_out
    sgemm128<<<gQ, 256>>>(A, wout, out, ROWS, CD, CD);
}

// round 17
// speedup vs baseline: 1.0951x; 1.0929x over previous
#include <cuda_runtime.h>
#include <math.h>

#define BZ 2
#define NS 2048
#define CD 1024
#define HH 16
#define DD 64
#define ROWS (BZ*NS)   // 4096

typedef unsigned long long ull;

// Scratch (device globals; no allocation allowed)
__device__ float  g_Q  [ROWS*CD];     // 16 MB  post-proj Q (raw; RoPE fused into flash)
__device__ float  g_KV [ROWS*2*DD];   //  2 MB  per row: K[64] | V[64] (g-summed)
__device__ float  g_W  [CD*2*DD];     // 512 KB effective KV weight (g-summed)
__device__ float  g_A  [ROWS*CD];     // 16 MB  attention output [B*N, H*D]
__device__ float2 g_tab[NS*32];       // 512 KB cos/sin table per (pos, pair)

// ---------------------------------------------------------------------------
// f32x2 packed helpers (sm_100+ PTX)
// ---------------------------------------------------------------------------
__device__ __forceinline__ ull pk(float lo, float hi) {
    ull r; asm("mov.b64 %0, {%1,%2};" : "=l"(r) : "f"(lo), "f"(hi)); return r;
}
__device__ __forceinline__ float2 upk(ull v) {
    float2 r; asm("mov.b64 {%0,%1}, %2;" : "=f"(r.x), "=f"(r.y) : "l"(v)); return r;
}
__device__ __forceinline__ ull fma2(ull a, ull b, ull c) {
    ull d; asm("fma.rn.f32x2 %0, %1, %2, %3;" : "=l"(d) : "l"(a), "l"(b), "l"(c)); return d;
}
__device__ __forceinline__ ull mul2(ull a, ull b) {
    ull d; asm("mul.rn.f32x2 %0, %1, %2;" : "=l"(d) : "l"(a), "l"(b)); return d;
}
__device__ __forceinline__ ull add2(ull a, ull b) {
    ull d; asm("add.rn.f32x2 %0, %1, %2;" : "=l"(d) : "l"(a), "l"(b)); return d;
}

// ---------------------------------------------------------------------------
// RoPE cos/sin table: double-precision angles, 65536 entries (one-time cheap)
// ---------------------------------------------------------------------------
__global__ void tab_kernel() {
    int idx = blockIdx.x * blockDim.x + threadIdx.x;
    if (idx >= NS * 32) return;
    int pos = idx >> 5, i = idx & 31;
    double inv = pow(10000.0, -(double)(2 * i) / (double)DD);
    double a = (double)pos * inv;
    g_tab[idx] = make_float2((float)cos(a), (float)sin(a));
}

// ---------------------------------------------------------------------------
// Fold the kv-head sum into the weight: W_eff[c][j] (j<64 -> K, j>=64 -> V)
// ---------------------------------------------------------------------------
__global__ void weff_kernel(const float* __restrict__ wkv) {
    int idx = blockIdx.x * blockDim.x + threadIdx.x;
    if (idx >= CD * 128) return;
    int c = idx >> 7, j = idx & 127;
    const float* b = wkv + (size_t)c * 512 + ((j < 64) ? j : (256 + (j - 64)));
    g_W[idx] = b[0] + b[64] + b[128] + b[192];
}

// ---------------------------------------------------------------------------
// RoPE apply (table lookup) on K half of KV, in place.
// ---------------------------------------------------------------------------
__global__ void ropekv_kernel() {
    int idx = blockIdx.x * blockDim.x + threadIdx.x;
    if (idx >= ROWS * 32) return;
    int i = idx & 31, row = idx >> 5;
    int pos = row & (NS - 1);
    float2 cs = g_tab[pos * 32 + i];
    float* p1 = g_KV + (size_t)row * 128 + i;
    float* p2 = p1 + 32;
    float x1 = *p1, x2 = *p2;
    *p1 = x1 * cs.x - x2 * cs.y;
    *p2 = x2 * cs.x + x1 * cs.y;
}

// ---------------------------------------------------------------------------
// 128x128x8 SGEMM with packed f32x2 FMAs. A stored in smem PRE-DUPLICATED
// (each element as a packed (a,a) pair) so LDS.128 yields broadcast operands
// directly. 256 threads, each computes an 8x8 output tile as 8x4 f32x2 accs.
// ---------------------------------------------------------------------------
__global__ __launch_bounds__(256) void sgemm128x2(
    const float* __restrict__ A, const float* __restrict__ Bm,
    float* __restrict__ Cm, int M, int Nn, int K)
{
    __shared__ ull   As2[8][128];   // 8 KB, duplicated-pair A
    __shared__ float Bs [8][128];   // 4 KB
    const int brow = blockIdx.y * 128;
    const int bcol = blockIdx.x * 128;
    const int tid  = threadIdx.x;

    const int a_r = tid >> 1,  a_k = (tid & 1) * 4;   // A tile 128x8 via float4
    const int b_k = tid >> 5,  b_c = (tid & 31) * 4;  // B tile 8x128 via float4
    const int ty  = tid >> 4,  tx  = tid & 15;

    ull acc2[8][4];
    #pragma unroll
    for (int i = 0; i < 8; i++)
        #pragma unroll
        for (int j = 0; j < 4; j++) acc2[i][j] = 0ull;

    for (int k0 = 0; k0 < K; k0 += 8) {
        float4 av = *(const float4*)(A + (size_t)(brow + a_r) * K + k0 + a_k);
        As2[a_k + 0][a_r] = pk(av.x, av.x);
        As2[a_k + 1][a_r] = pk(av.y, av.y);
        As2[a_k + 2][a_r] = pk(av.z, av.z);
        As2[a_k + 3][a_r] = pk(av.w, av.w);
        *(float4*)(&Bs[b_k][b_c]) =
            *(const float4*)(Bm + (size_t)(k0 + b_k) * Nn + bcol + b_c);
        __syncthreads();

        #pragma unroll
        for (int kk = 0; kk < 8; kk++) {
            ull ar2[8], br2[4];
            const ulonglong2* a4 = (const ulonglong2*)(&As2[kk][ty * 8]);
            #pragma unroll
            for (int q = 0; q < 4; q++) {
                ulonglong2 v = a4[q];
                ar2[2*q] = v.x; ar2[2*q+1] = v.y;
            }
            const ulonglong2* b4 = (const ulonglong2*)(&Bs[kk][tx * 8]);
            ulonglong2 bA = b4[0], bB = b4[1];
            br2[0] = bA.x; br2[1] = bA.y; br2[2] = bB.x; br2[3] = bB.y;
            #pragma unroll
            for (int i = 0; i < 8; i++)
                #pragma unroll
                for (int j = 0; j < 4; j++)
                    acc2[i][j] = fma2(ar2[i], br2[j], acc2[i][j]);
        }
        __syncthreads();
    }

    #pragma unroll
    for (int i = 0; i < 8; i++) {
        ulonglong2* dst = (ulonglong2*)(Cm + (size_t)(brow + ty * 8 + i) * Nn + bcol + tx * 8);
        ulonglong2 s0; s0.x = acc2[i][0]; s0.y = acc2[i][1];
        ulonglong2 s1; s1.x = acc2[i][2]; s1.y = acc2[i][3];
        dst[0] = s0; dst[1] = s1;
    }
}

// ---------------------------------------------------------------------------
// Flash attention with packed f32x2 math. 1 thread = 1 query row.
// Q-RoPE fused into the load (raw Q in, table lookup). q,o packed in regs.
// grid = (NS/128, HH, BZ), block = 128.
// ---------------------------------------------------------------------------
__global__ __launch_bounds__(128) void flash_kernel() {
    __shared__ float Ks[64][64];
    __shared__ float Vs[64][64];

    const int t = threadIdx.x;
    const int n = blockIdx.x * 128 + t;
    const int h = blockIdx.y;
    const int b = blockIdx.z;

    // Load raw Q row, apply RoPE (table) + scale, pack into 32 f32x2 pairs
    const float* qptr = g_Q + ((size_t)(b * NS + n)) * CD + h * DD;
    float qa[64];
    #pragma unroll
    for (int d4 = 0; d4 < 16; d4++) {
        float4 v = ((const float4*)qptr)[d4];
        qa[d4*4+0] = v.x; qa[d4*4+1] = v.y; qa[d4*4+2] = v.z; qa[d4*4+3] = v.w;
    }
    const float2* tb = g_tab + (size_t)n * 32;
    #pragma unroll
    for (int i = 0; i < 32; i++) {
        float2 cs = tb[i];
        float x1 = qa[i], x2 = qa[i + 32];
        qa[i]      = (x1 * cs.x - x2 * cs.y) * 0.125f;
        qa[i + 32] = (x2 * cs.x + x1 * cs.y) * 0.125f;
    }
    ull qp[32], o2[32];
    #pragma unroll
    for (int q = 0; q < 32; q++) { qp[q] = pk(qa[2*q], qa[2*q+1]); o2[q] = 0ull; }

    float m = -INFINITY, l = 0.f;
    const float* KVb = g_KV + (size_t)b * NS * 128;

    for (int jt = 0; jt < NS; jt += 64) {
        #pragma unroll
        for (int i2 = 0; i2 < 8; i2++) {
            int flat = t + i2 * 128;            // 0..1023
            int j = flat >> 4, d4 = flat & 15;
            const float4* src = (const float4*)(KVb + (size_t)(jt + j) * 128);
            ((float4*)Ks[j])[d4] = src[d4];
            ((float4*)Vs[j])[d4] = src[16 + d4];
        }
        __syncthreads();

        for (int j = 0; j < 64; j++) {
            const ulonglong2* kr = (const ulonglong2*)Ks[j];
            ull a0 = 0ull, a1 = 0ull, a2 = 0ull, a3 = 0ull;
            #pragma unroll
            for (int q = 0; q < 16; q += 2) {
                ulonglong2 ka = kr[q], kb = kr[q + 1];
                a0 = fma2(qp[2*q + 0], ka.x, a0);
                a1 = fma2(qp[2*q + 1], ka.y, a1);
                a2 = fma2(qp[2*q + 2], kb.x, a2);
                a3 = fma2(qp[2*q + 3], kb.y, a3);
            }
            ull st = add2(add2(a0, a1), add2(a2, a3));
            float2 sf = upk(st);
            float s = sf.x + sf.y;

            if (s > m) {                      // rare rescale path
                float corr = __expf(m - s);
                m = s;
                l *= corr;
                ull c2 = pk(corr, corr);
                #pragma unroll
                for (int q = 0; q < 32; q++) o2[q] = mul2(o2[q], c2);
            }
            float p = __expf(s - m);
            l += p;
            ull p2 = pk(p, p);
            const ulonglong2* vr = (const ulonglong2*)Vs[j];
            #pragma unroll
            for (int q = 0; q < 16; q++) {
                ulonglong2 vv = vr[q];
                o2[2*q + 0] = fma2(p2, vv.x, o2[2*q + 0]);
                o2[2*q + 1] = fma2(p2, vv.y, o2[2*q + 1]);
            }
        }
        __syncthreads();
    }

    float inv = 1.f / l;
    ull inv2 = pk(inv, inv);
    float* optr = g_A + ((size_t)(b * NS + n)) * CD + h * DD;
    #pragma unroll
    for (int q = 0; q < 8; q++) {
        ulonglong2 r;
        r.x = mul2(o2[4*q + 0], inv2);
        r.y = mul2(o2[4*q + 1], inv2);
        ((ulonglong2*)optr)[2*q + 0] = r;
        r.x = mul2(o2[4*q + 2], inv2);
        r.y = mul2(o2[4*q + 3], inv2);
        ((ulonglong2*)optr)[2*q + 1] = r;
    }
}

// ---------------------------------------------------------------------------
extern "C" void kernel_launch(void* const* d_in, const int* in_sizes, int n_in,
                              void* d_out, int out_size) {
    const float* x    = (const float*)d_in[0];
    const float* wq   = (const float*)d_in[1];
    const float* wkv  = (const float*)d_in[2];
    const float* wout = (const float*)d_in[3];
    float* out = (float*)d_out;

    float *Q, *KV, *W, *A;
    cudaGetSymbolAddress((void**)&Q,  g_Q);
    cudaGetSymbolAddress((void**)&KV, g_KV);
    cudaGetSymbolAddress((void**)&W,  g_W);
    cudaGetSymbolAddress((void**)&A,  g_A);

    // 0) RoPE table (double-precision angles, computed once per launch)
    tab_kernel<<<(NS * 32) / 256, 256>>>();

    // 1) fold kv-head sum into weight
    weff_kernel<<<(CD * 128) / 256, 256>>>(wkv);

    // 2) Q = x @ w_q   [4096x1024]
    dim3 gQ(CD / 128, ROWS / 128);
    sgemm128x2<<<gQ, 256>>>(x, wq, Q, ROWS, CD, CD);

    // 3) KV = x @ W_eff   [4096x128]
    dim3 gKV(1, ROWS / 128);
    sgemm128x2<<<gKV, 256>>>(x, W, KV, ROWS, 128, CD);

    // 4) RoPE on K half of KV (Q RoPE is fused into flash)
    ropekv_kernel<<<(ROWS * 32) / 256, 256>>>();

    // 5) flash attention -> g_A  [B*N, H*D]
    dim3 gF(NS / 128, HH, BZ);
    flash_kernel<<<gF, 128>>>();

    // 6) out = A @ w_out
    sgemm128x2<<<gQ, 256>>>(A, wout, out, ROWS, CD, CD);
}